// round 1
// baseline (speedup 1.0000x reference)
#include <cuda_runtime.h>
#include <cuda_bf16.h>
#include <math.h>

#define NN 100000
#define EE 1600000
#define ET 1700000      // edges + self loops
#define H 14
#define C 7
#define HC 98
#define FIN 256

// ---------------- scratch (device globals; reused across both layers) ----------
__device__ float g_xh[NN * HC];      // projected features [N,H,C]
__device__ float g_alsrc[NN * H];    // per-node src logits
__device__ float g_aldst[NN * H];    // per-node dst logits
__device__ float g_amax[NN * H];     // segment max of edge logits
__device__ float g_den[NN * H];      // softmax denominators
__device__ float g_agg[NN * HC];     // segment-max aggregated messages
__device__ float g_h[NN * C];        // layer-1 output features

#define NEG_INF __int_as_float(0xff800000)

__device__ __forceinline__ void atomicMaxFloat(float* addr, float v) {
    // works for all finite floats with -inf init
    if (v >= 0.0f) atomicMax((int*)addr, __float_as_int(v));
    else           atomicMin((unsigned int*)addr, __float_as_uint(v));
}

__device__ __forceinline__ float lrelu(float v) {
    return v > 0.0f ? v : 0.2f * v;
}

// ---------------- GEMM1: x[N,256] @ W1[256,98] -> g_xh -------------------------
// BM=64 rows, BN=128 cols (98 used), BK=16, 256 threads, 8x4 micro-tile
__global__ void k_gemm1(const float* __restrict__ x, const float* __restrict__ W) {
    __shared__ float xs[16][68];   // [BK][BM+pad]
    __shared__ float ws[16][128];  // [BK][BN]
    const int bm = blockIdx.x * 64;
    const int tid = threadIdx.x;
    const int ct = tid & 31;       // col group (4 cols each)
    const int rt = tid >> 5;       // row group (8 rows each)
    float acc[8][4];
#pragma unroll
    for (int i = 0; i < 8; i++)
#pragma unroll
        for (int j = 0; j < 4; j++) acc[i][j] = 0.0f;

    for (int k0 = 0; k0 < FIN; k0 += 16) {
        // load x tile: 64x16
        {
            const int kk = tid & 15;
            const int mb = tid >> 4;
#pragma unroll
            for (int j = 0; j < 4; j++) {
                const int m = mb + j * 16;
                const int row = bm + m;
                xs[kk][m] = (row < NN) ? x[row * FIN + k0 + kk] : 0.0f;
            }
        }
        // load W tile: 16x128 (zero-pad cols >= 98)
        {
            const int c = tid & 127;
            for (int j = tid >> 7; j < 16; j += 2)
                ws[j][c] = (c < HC) ? W[(k0 + j) * HC + c] : 0.0f;
        }
        __syncthreads();
#pragma unroll
        for (int k = 0; k < 16; k++) {
            float a[8], b[4];
            const float4 a0 = *(const float4*)&xs[k][rt * 8];
            const float4 a1 = *(const float4*)&xs[k][rt * 8 + 4];
            a[0]=a0.x; a[1]=a0.y; a[2]=a0.z; a[3]=a0.w;
            a[4]=a1.x; a[5]=a1.y; a[6]=a1.z; a[7]=a1.w;
            const float4 b0 = *(const float4*)&ws[k][ct * 4];
            b[0]=b0.x; b[1]=b0.y; b[2]=b0.z; b[3]=b0.w;
#pragma unroll
            for (int i = 0; i < 8; i++)
#pragma unroll
                for (int j = 0; j < 4; j++) acc[i][j] = fmaf(a[i], b[j], acc[i][j]);
        }
        __syncthreads();
    }
#pragma unroll
    for (int i = 0; i < 8; i++) {
        const int row = bm + rt * 8 + i;
        if (row >= NN) continue;
#pragma unroll
        for (int j = 0; j < 4; j++) {
            const int col = ct * 4 + j;
            if (col < HC) g_xh[row * HC + col] = acc[i][j];
        }
    }
}

// ---------------- per-node attention logits ------------------------------------
__global__ void k_al(const float* __restrict__ a_src, const float* __restrict__ a_dst) {
    const int i = blockIdx.x * blockDim.x + threadIdx.x;
    if (i >= NN * H) return;
    const int n = i / H, h = i % H;
    const float* xr = &g_xh[n * HC + h * C];
    float s1 = 0.0f, s2 = 0.0f;
#pragma unroll
    for (int c = 0; c < C; c++) {
        const float v = xr[c];
        s1 = fmaf(v, a_src[h * C + c], s1);
        s2 = fmaf(v, a_dst[h * C + c], s2);
    }
    g_alsrc[i] = s1;
    g_aldst[i] = s2;
}

// ---------------- init segment buffers -----------------------------------------
__global__ void k_init() {
    const int i = blockIdx.x * blockDim.x + threadIdx.x;
    if (i >= NN * HC) return;
    g_agg[i] = NEG_INF;
    if (i < NN * H) { g_amax[i] = NEG_INF; g_den[i] = 0.0f; }
}

// ---------------- edge pass 1: segment max of logits ---------------------------
__global__ void k_edge1(const int* __restrict__ ei) {
    const int e = blockIdx.x * blockDim.x + threadIdx.x;
    if (e >= ET) return;
    int s, d;
    if (e < EE) { s = ei[e]; d = ei[EE + e]; } else { s = d = e - EE; }
    const float* as = &g_alsrc[s * H];
    const float* ad = &g_aldst[d * H];
    float* am = &g_amax[d * H];
#pragma unroll
    for (int h = 0; h < H; h++) {
        const float v = lrelu(as[h] + ad[h]);
        atomicMaxFloat(&am[h], v);
    }
}

// ---------------- edge pass 2: exp-sum -----------------------------------------
__global__ void k_edge2(const int* __restrict__ ei) {
    const int e = blockIdx.x * blockDim.x + threadIdx.x;
    if (e >= ET) return;
    int s, d;
    if (e < EE) { s = ei[e]; d = ei[EE + e]; } else { s = d = e - EE; }
    const float* as = &g_alsrc[s * H];
    const float* ad = &g_aldst[d * H];
    const float* am = &g_amax[d * H];
    float* dn = &g_den[d * H];
#pragma unroll
    for (int h = 0; h < H; h++) {
        const float v = lrelu(as[h] + ad[h]);
        atomicAdd(&dn[h], __expf(v - am[h]));
    }
}

// ---------------- edge pass 3: weighted message segment-max --------------------
__global__ void k_edge3(const int* __restrict__ ei) {
    const int e = blockIdx.x * blockDim.x + threadIdx.x;
    if (e >= ET) return;
    int s, d;
    if (e < EE) { s = ei[e]; d = ei[EE + e]; } else { s = d = e - EE; }
    const float* as = &g_alsrc[s * H];
    const float* ad = &g_aldst[d * H];
    const float* am = &g_amax[d * H];
    const float* dn = &g_den[d * H];
    const float* xr = &g_xh[s * HC];
    float* ag = &g_agg[d * HC];
#pragma unroll
    for (int h = 0; h < H; h++) {
        const float v = lrelu(as[h] + ad[h]);
        const float a = __expf(v - am[h]) / dn[h];
#pragma unroll
        for (int c = 0; c < C; c++)
            atomicMaxFloat(&ag[h * C + c], a * xr[h * C + c]);
    }
}

// ---------------- finalize layer 1: mean over heads + bias + relu --------------
__global__ void k_fin1(const float* __restrict__ b) {
    const int i = blockIdx.x * blockDim.x + threadIdx.x;
    if (i >= NN * C) return;
    const int n = i / C, c = i % C;
    float s = 0.0f;
#pragma unroll
    for (int h = 0; h < H; h++) s += g_agg[n * HC + h * C + c];
    g_h[i] = fmaxf(s * (1.0f / H) + b[c], 0.0f);
}

// ---------------- GEMM2: g_h[N,7] @ W2[7,98] -> g_xh ---------------------------
__global__ void k_gemm2(const float* __restrict__ W2) {
    const int i = blockIdx.x * blockDim.x + threadIdx.x;
    if (i >= NN * HC) return;
    const int n = i / HC, c = i % HC;
    float s = 0.0f;
#pragma unroll
    for (int k = 0; k < C; k++) s = fmaf(g_h[n * C + k], W2[k * HC + c], s);
    g_xh[i] = s;
}

// ---------------- finalize layer 2: mean + bias + log_softmax ------------------
__global__ void k_fin2(const float* __restrict__ b, float* __restrict__ out) {
    const int n = blockIdx.x * blockDim.x + threadIdx.x;
    if (n >= NN) return;
    float v[C];
#pragma unroll
    for (int c = 0; c < C; c++) {
        float s = 0.0f;
#pragma unroll
        for (int h = 0; h < H; h++) s += g_agg[n * HC + h * C + c];
        v[c] = s * (1.0f / H) + b[c];
    }
    float mx = v[0];
#pragma unroll
    for (int c = 1; c < C; c++) mx = fmaxf(mx, v[c]);
    float se = 0.0f;
#pragma unroll
    for (int c = 0; c < C; c++) se += __expf(v[c] - mx);
    const float lse = mx + logf(se);
#pragma unroll
    for (int c = 0; c < C; c++) out[n * C + c] = v[c] - lse;
}

extern "C" void kernel_launch(void* const* d_in, const int* in_sizes, int n_in,
                              void* d_out, int out_size) {
    const float* x      = (const float*)d_in[0];
    const int*   ei     = (const int*)  d_in[1];
    const float* W1     = (const float*)d_in[2];
    const float* a_src1 = (const float*)d_in[3];
    const float* a_dst1 = (const float*)d_in[4];
    const float* b1     = (const float*)d_in[5];
    const float* W2     = (const float*)d_in[6];
    const float* a_src2 = (const float*)d_in[7];
    const float* a_dst2 = (const float*)d_in[8];
    const float* b2     = (const float*)d_in[9];
    float* out = (float*)d_out;

    const int EB = (ET + 255) / 256;

    // ----- layer 1 -----
    k_gemm1<<<(NN + 63) / 64, 256>>>(x, W1);
    k_al   <<<(NN * H + 255) / 256, 256>>>(a_src1, a_dst1);
    k_init <<<(NN * HC + 255) / 256, 256>>>();
    k_edge1<<<EB, 256>>>(ei);
    k_edge2<<<EB, 256>>>(ei);
    k_edge3<<<EB, 256>>>(ei);
    k_fin1 <<<(NN * C + 255) / 256, 256>>>(b1);

    // ----- layer 2 -----
    k_gemm2<<<(NN * HC + 255) / 256, 256>>>(W2);
    k_al   <<<(NN * H + 255) / 256, 256>>>(a_src2, a_dst2);
    k_init <<<(NN * HC + 255) / 256, 256>>>();
    k_edge1<<<EB, 256>>>(ei);
    k_edge2<<<EB, 256>>>(ei);
    k_edge3<<<EB, 256>>>(ei);
    k_fin2 <<<(NN + 255) / 256, 256>>>(b2, out);
}

// round 2
// speedup vs baseline: 8.0077x; 8.0077x over previous
#include <cuda_runtime.h>
#include <cuda_bf16.h>
#include <math.h>

#define NN 100000
#define EE 1600000
#define ET 1700000      // edges + self loops
#define H 14
#define C 7
#define HC 98
#define FIN 256

// ---------------- scratch (device globals; reused across both layers) ----------
__device__ float g_xh[NN * HC];      // projected features [N,H,C]
__device__ float g_alsrc[NN * H];    // per-node src logits
__device__ float g_aldst[NN * H];    // per-node dst logits
__device__ float g_agg[NN * HC];     // per-head attention outputs
__device__ float g_h[NN * C];        // layer-1 output features

// CSR-by-destination scratch
__device__ int g_cnt[NN];
__device__ int g_woff[NN];
__device__ int g_rp[NN + 1];
__device__ int g_bsum[128];
__device__ int g_csrc[ET];

#define NEG_INF __int_as_float(0xff800000)

__device__ __forceinline__ float lrelu(float v) {
    return v > 0.0f ? v : 0.2f * v;
}

// ---------------- GEMM1: x[N,256] @ W1[256,98] -> g_xh -------------------------
__global__ void k_gemm1(const float* __restrict__ x, const float* __restrict__ W) {
    __shared__ float xs[16][68];   // [BK][BM+pad]
    __shared__ float ws[16][128];  // [BK][BN]
    const int bm = blockIdx.x * 64;
    const int tid = threadIdx.x;
    const int ct = tid & 31;       // col group (4 cols each)
    const int rt = tid >> 5;       // row group (8 rows each)
    float acc[8][4];
#pragma unroll
    for (int i = 0; i < 8; i++)
#pragma unroll
        for (int j = 0; j < 4; j++) acc[i][j] = 0.0f;

    for (int k0 = 0; k0 < FIN; k0 += 16) {
        {
            const int kk = tid & 15;
            const int mb = tid >> 4;
#pragma unroll
            for (int j = 0; j < 4; j++) {
                const int m = mb + j * 16;
                const int row = bm + m;
                xs[kk][m] = (row < NN) ? x[row * FIN + k0 + kk] : 0.0f;
            }
        }
        {
            const int c = tid & 127;
            for (int j = tid >> 7; j < 16; j += 2)
                ws[j][c] = (c < HC) ? W[(k0 + j) * HC + c] : 0.0f;
        }
        __syncthreads();
#pragma unroll
        for (int k = 0; k < 16; k++) {
            float a[8], b[4];
            const float4 a0 = *(const float4*)&xs[k][rt * 8];
            const float4 a1 = *(const float4*)&xs[k][rt * 8 + 4];
            a[0]=a0.x; a[1]=a0.y; a[2]=a0.z; a[3]=a0.w;
            a[4]=a1.x; a[5]=a1.y; a[6]=a1.z; a[7]=a1.w;
            const float4 b0 = *(const float4*)&ws[k][ct * 4];
            b[0]=b0.x; b[1]=b0.y; b[2]=b0.z; b[3]=b0.w;
#pragma unroll
            for (int i = 0; i < 8; i++)
#pragma unroll
                for (int j = 0; j < 4; j++) acc[i][j] = fmaf(a[i], b[j], acc[i][j]);
        }
        __syncthreads();
    }
#pragma unroll
    for (int i = 0; i < 8; i++) {
        const int row = bm + rt * 8 + i;
        if (row >= NN) continue;
#pragma unroll
        for (int j = 0; j < 4; j++) {
            const int col = ct * 4 + j;
            if (col < HC) g_xh[row * HC + col] = acc[i][j];
        }
    }
}

// ---------------- per-node attention logits ------------------------------------
__global__ void k_al(const float* __restrict__ a_src, const float* __restrict__ a_dst) {
    const int i = blockIdx.x * blockDim.x + threadIdx.x;
    if (i >= NN * H) return;
    const int n = i / H, h = i % H;
    const float* xr = &g_xh[n * HC + h * C];
    float s1 = 0.0f, s2 = 0.0f;
#pragma unroll
    for (int c = 0; c < C; c++) {
        const float v = xr[c];
        s1 = fmaf(v, a_src[h * C + c], s1);
        s2 = fmaf(v, a_dst[h * C + c], s2);
    }
    g_alsrc[i] = s1;
    g_aldst[i] = s2;
}

// ---------------- CSR build ----------------------------------------------------
__global__ void k_zero() {
    const int i = blockIdx.x * blockDim.x + threadIdx.x;
    if (i < NN) { g_cnt[i] = 0; g_woff[i] = 0; }
}

__global__ void k_hist(const int* __restrict__ ei) {
    const int e = blockIdx.x * blockDim.x + threadIdx.x;
    if (e >= ET) return;
    const int d = (e < EE) ? ei[EE + e] : (e - EE);
    atomicAdd(&g_cnt[d], 1);
}

// block-wise inclusive scan (1024 elems per block)
__global__ void k_scan1() {
    __shared__ int sm[1024];
    const int t = threadIdx.x;
    const int i = blockIdx.x * 1024 + t;
    int v = (i < NN) ? g_cnt[i] : 0;
    sm[t] = v;
#pragma unroll
    for (int off = 1; off < 1024; off <<= 1) {
        __syncthreads();
        int add = (t >= off) ? sm[t - off] : 0;
        __syncthreads();
        sm[t] += add;
    }
    __syncthreads();
    if (i < NN) g_rp[i + 1] = sm[t];
    if (t == 1023) g_bsum[blockIdx.x] = sm[1023];
}

__global__ void k_scan2(int nblocks) {
    if (threadIdx.x == 0 && blockIdx.x == 0) {
        int run = 0;
        for (int b = 0; b < nblocks; b++) {
            const int t = g_bsum[b];
            g_bsum[b] = run;
            run += t;
        }
    }
}

__global__ void k_scan3() {
    const int i = blockIdx.x * blockDim.x + threadIdx.x;
    if (i == 0) g_rp[0] = 0;
    if (i < NN) g_rp[i + 1] += g_bsum[i >> 10];
}

__global__ void k_scatter(const int* __restrict__ ei) {
    const int e = blockIdx.x * blockDim.x + threadIdx.x;
    if (e >= ET) return;
    int s, d;
    if (e < EE) { s = ei[e]; d = ei[EE + e]; } else { s = d = e - EE; }
    const int pos = g_rp[d] + atomicAdd(&g_woff[d], 1);
    g_csrc[pos] = s;
}

// ---------------- fused per-(node,head) online softmax + max aggregation -------
__global__ void k_node() {
    const int i = blockIdx.x * blockDim.x + threadIdx.x;
    if (i >= NN * H) return;
    const int n = i / H, h = i % H;
    const int beg = g_rp[n], end = g_rp[n + 1];
    const float ad = g_aldst[i];

    // first edge (deg >= 1 thanks to self loops)
    int s = g_csrc[beg];
    float m = lrelu(g_alsrc[s * H + h] + ad);
    float den = 1.0f;
    float agg[C];
    {
        const float* xr = &g_xh[s * HC + h * C];
#pragma unroll
        for (int c = 0; c < C; c++) agg[c] = xr[c];
    }

    for (int j = beg + 1; j < end; j++) {
        s = g_csrc[j];
        const float l = lrelu(g_alsrc[s * H + h] + ad);
        const float* xr = &g_xh[s * HC + h * C];
        float w;
        if (l > m) {
            const float sc = __expf(m - l);
            den *= sc;
#pragma unroll
            for (int c = 0; c < C; c++) agg[c] *= sc;
            m = l;
            w = 1.0f;
        } else {
            w = __expf(l - m);
        }
        den += w;
#pragma unroll
        for (int c = 0; c < C; c++) agg[c] = fmaxf(agg[c], w * xr[c]);
    }

    const float inv = 1.0f / den;
    float* og = &g_agg[n * HC + h * C];
#pragma unroll
    for (int c = 0; c < C; c++) og[c] = agg[c] * inv;
}

// ---------------- finalize layer 1: mean over heads + bias + relu --------------
__global__ void k_fin1(const float* __restrict__ b) {
    const int i = blockIdx.x * blockDim.x + threadIdx.x;
    if (i >= NN * C) return;
    const int n = i / C, c = i % C;
    float s = 0.0f;
#pragma unroll
    for (int h = 0; h < H; h++) s += g_agg[n * HC + h * C + c];
    g_h[i] = fmaxf(s * (1.0f / H) + b[c], 0.0f);
}

// ---------------- GEMM2: g_h[N,7] @ W2[7,98] -> g_xh ---------------------------
__global__ void k_gemm2(const float* __restrict__ W2) {
    const int i = blockIdx.x * blockDim.x + threadIdx.x;
    if (i >= NN * HC) return;
    const int n = i / HC, c = i % HC;
    float s = 0.0f;
#pragma unroll
    for (int k = 0; k < C; k++) s = fmaf(g_h[n * C + k], W2[k * HC + c], s);
    g_xh[i] = s;
}

// ---------------- finalize layer 2: mean + bias + log_softmax ------------------
__global__ void k_fin2(const float* __restrict__ b, float* __restrict__ out) {
    const int n = blockIdx.x * blockDim.x + threadIdx.x;
    if (n >= NN) return;
    float v[C];
#pragma unroll
    for (int c = 0; c < C; c++) {
        float s = 0.0f;
#pragma unroll
        for (int h = 0; h < H; h++) s += g_agg[n * HC + h * C + c];
        v[c] = s * (1.0f / H) + b[c];
    }
    float mx = v[0];
#pragma unroll
    for (int c = 1; c < C; c++) mx = fmaxf(mx, v[c]);
    float se = 0.0f;
#pragma unroll
    for (int c = 0; c < C; c++) se += __expf(v[c] - mx);
    const float lse = mx + logf(se);
#pragma unroll
    for (int c = 0; c < C; c++) out[n * C + c] = v[c] - lse;
}

extern "C" void kernel_launch(void* const* d_in, const int* in_sizes, int n_in,
                              void* d_out, int out_size) {
    const float* x      = (const float*)d_in[0];
    const int*   ei     = (const int*)  d_in[1];
    const float* W1     = (const float*)d_in[2];
    const float* a_src1 = (const float*)d_in[3];
    const float* a_dst1 = (const float*)d_in[4];
    const float* b1     = (const float*)d_in[5];
    const float* W2     = (const float*)d_in[6];
    const float* a_src2 = (const float*)d_in[7];
    const float* a_dst2 = (const float*)d_in[8];
    const float* b2     = (const float*)d_in[9];
    float* out = (float*)d_out;

    const int EB = (ET + 255) / 256;
    const int SCAN_BLOCKS = (NN + 1023) / 1024;

    // ----- CSR by destination (shared by both layers) -----
    k_zero   <<<(NN + 255) / 256, 256>>>();
    k_hist   <<<EB, 256>>>(ei);
    k_scan1  <<<SCAN_BLOCKS, 1024>>>();
    k_scan2  <<<1, 32>>>(SCAN_BLOCKS);
    k_scan3  <<<(NN + 255) / 256, 256>>>();
    k_scatter<<<EB, 256>>>(ei);

    // ----- layer 1 -----
    k_gemm1<<<(NN + 63) / 64, 256>>>(x, W1);
    k_al   <<<(NN * H + 255) / 256, 256>>>(a_src1, a_dst1);
    k_node <<<(NN * H + 255) / 256, 256>>>();
    k_fin1 <<<(NN * C + 255) / 256, 256>>>(b1);

    // ----- layer 2 -----
    k_gemm2<<<(NN * HC + 255) / 256, 256>>>(W2);
    k_al   <<<(NN * H + 255) / 256, 256>>>(a_src2, a_dst2);
    k_node <<<(NN * H + 255) / 256, 256>>>();
    k_fin2 <<<(NN + 255) / 256, 256>>>(b2, out);
}

// round 3
// speedup vs baseline: 8.3847x; 1.0471x over previous
#include <cuda_runtime.h>
#include <cuda_bf16.h>
#include <math.h>

#define NN 100000
#define EE 1600000
#define ET 1700000      // edges + self loops
#define H 14
#define C 7
#define HC 98
#define CP 8            // padded channels
#define HCP 112         // H * CP
#define FIN 256

// ---------------- scratch (device globals; reused across both layers) ----------
__device__ float g_xh[NN * HCP];     // projected features [N,H,8] (ch 7 = pad, stays 0)
__device__ float g_alsrc[NN * H];    // per-node src logits
__device__ float g_aldst[NN * H];    // per-node dst logits
__device__ float g_h[NN * C];        // layer-1 output features

// CSR-by-destination scratch
__device__ int g_cnt[NN];
__device__ int g_woff[NN];           // exclusive offsets (consumed by scatter)
__device__ int g_rp[NN + 1];
__device__ int g_bsum[128];
__device__ int g_csrc[ET];

__device__ __forceinline__ float lrelu(float v) {
    return v > 0.0f ? v : 0.2f * v;
}

// ---------------- GEMM1: x[N,256] @ W1[256,98] -> g_xh (padded) ----------------
__global__ void k_gemm1(const float* __restrict__ x, const float* __restrict__ W) {
    __shared__ float xs[16][68];   // [BK][BM+pad]
    __shared__ float ws[16][128];  // [BK][BN]
    const int bm = blockIdx.x * 64;
    const int tid = threadIdx.x;
    const int ct = tid & 31;       // col group (4 cols each)
    const int rt = tid >> 5;       // row group (8 rows each)
    float acc[8][4];
#pragma unroll
    for (int i = 0; i < 8; i++)
#pragma unroll
        for (int j = 0; j < 4; j++) acc[i][j] = 0.0f;

    for (int k0 = 0; k0 < FIN; k0 += 16) {
        {
            const int kk = tid & 15;
            const int mb = tid >> 4;
#pragma unroll
            for (int j = 0; j < 4; j++) {
                const int m = mb + j * 16;
                const int row = bm + m;
                xs[kk][m] = (row < NN) ? x[row * FIN + k0 + kk] : 0.0f;
            }
        }
        {
            const int c = tid & 127;
            for (int j = tid >> 7; j < 16; j += 2)
                ws[j][c] = (c < HC) ? W[(k0 + j) * HC + c] : 0.0f;
        }
        __syncthreads();
#pragma unroll
        for (int k = 0; k < 16; k++) {
            float a[8], b[4];
            const float4 a0 = *(const float4*)&xs[k][rt * 8];
            const float4 a1 = *(const float4*)&xs[k][rt * 8 + 4];
            a[0]=a0.x; a[1]=a0.y; a[2]=a0.z; a[3]=a0.w;
            a[4]=a1.x; a[5]=a1.y; a[6]=a1.z; a[7]=a1.w;
            const float4 b0 = *(const float4*)&ws[k][ct * 4];
            b[0]=b0.x; b[1]=b0.y; b[2]=b0.z; b[3]=b0.w;
#pragma unroll
            for (int i = 0; i < 8; i++)
#pragma unroll
                for (int j = 0; j < 4; j++) acc[i][j] = fmaf(a[i], b[j], acc[i][j]);
        }
        __syncthreads();
    }
#pragma unroll
    for (int i = 0; i < 8; i++) {
        const int row = bm + rt * 8 + i;
        if (row >= NN) continue;
#pragma unroll
        for (int j = 0; j < 4; j++) {
            const int col = ct * 4 + j;
            if (col < HC)
                g_xh[row * HCP + (col / C) * CP + (col % C)] = acc[i][j];
        }
    }
}

// ---------------- per-node attention logits (padded xh) ------------------------
__global__ void k_al(const float* __restrict__ a_src, const float* __restrict__ a_dst) {
    const int i = blockIdx.x * blockDim.x + threadIdx.x;
    if (i >= NN * H) return;
    const int n = i / H, h = i % H;
    const float* xr = &g_xh[n * HCP + h * CP];
    float s1 = 0.0f, s2 = 0.0f;
#pragma unroll
    for (int c = 0; c < C; c++) {
        const float v = xr[c];
        s1 = fmaf(v, a_src[h * C + c], s1);
        s2 = fmaf(v, a_dst[h * C + c], s2);
    }
    g_alsrc[i] = s1;
    g_aldst[i] = s2;
}

// ---------------- CSR build ----------------------------------------------------
__global__ void k_zero() {
    const int i = blockIdx.x * blockDim.x + threadIdx.x;
    if (i < NN) g_cnt[i] = 0;
}

__global__ void k_hist(const int* __restrict__ ei) {
    const int e = blockIdx.x * blockDim.x + threadIdx.x;
    if (e >= ET) return;
    const int d = (e < EE) ? ei[EE + e] : (e - EE);
    atomicAdd(&g_cnt[d], 1);
}

// block-wise inclusive scan (1024 elems per block)
__global__ void k_scan1() {
    __shared__ int sm[1024];
    const int t = threadIdx.x;
    const int i = blockIdx.x * 1024 + t;
    int v = (i < NN) ? g_cnt[i] : 0;
    sm[t] = v;
#pragma unroll
    for (int off = 1; off < 1024; off <<= 1) {
        __syncthreads();
        int add = (t >= off) ? sm[t - off] : 0;
        __syncthreads();
        sm[t] += add;
    }
    __syncthreads();
    if (i < NN) g_rp[i + 1] = sm[t];
    if (t == 1023) g_bsum[blockIdx.x] = sm[1023];
}

// warp-scan over block sums -> exclusive
__global__ void k_scan2(int nblocks) {
    const int lane = threadIdx.x;
    int run = 0;
    for (int base = 0; base < nblocks; base += 32) {
        const int idx = base + lane;
        const int orig = (idx < nblocks) ? g_bsum[idx] : 0;
        int v = orig;
#pragma unroll
        for (int off = 1; off < 32; off <<= 1) {
            const int t = __shfl_up_sync(0xffffffffu, v, off);
            if (lane >= off) v += t;
        }
        if (idx < nblocks) g_bsum[idx] = run + v - orig;  // exclusive
        run += __shfl_sync(0xffffffffu, v, 31);
    }
}

__global__ void k_scan3() {
    const int i = blockIdx.x * blockDim.x + threadIdx.x;
    if (i == 0) g_rp[0] = 0;
    if (i < NN) {
        const int inc = g_rp[i + 1] + g_bsum[i >> 10];
        g_rp[i + 1] = inc;
        g_woff[i] = inc - g_cnt[i];   // exclusive offset for scatter
    }
}

__global__ void k_scatter(const int* __restrict__ ei) {
    const int e = blockIdx.x * blockDim.x + threadIdx.x;
    if (e >= ET) return;
    int s, d;
    if (e < EE) { s = ei[e]; d = ei[EE + e]; } else { s = d = e - EE; }
    const int pos = atomicAdd(&g_woff[d], 1);
    g_csrc[pos] = s;
}

// ---------------- fused node pass: online softmax + max agg + head reduce ------
// MODE 0: write g_h with mean-head + bias + relu
// MODE 1: write final out with mean-head + bias + log_softmax
template<int MODE>
__global__ void k_node(const float* __restrict__ b, float* __restrict__ out) {
    __shared__ float sm[32][H][CP];          // 14 KB
    const int tid = threadIdx.x;             // 448 = 32 nodes * 14 heads
    const int ln = tid / H;                  // local node
    const int h  = tid % H;
    const int n  = blockIdx.x * 32 + ln;

    if (n < NN) {
        const int beg = g_rp[n], end = g_rp[n + 1];
        const float ad = g_aldst[n * H + h];
        float den = 0.0f;
        float4 agg0 = make_float4(-INFINITY, -INFINITY, -INFINITY, -INFINITY);
        float4 agg1 = agg0;
        for (int j = beg; j < end; j++) {
            const int s = g_csrc[j];
            const float l = lrelu(g_alsrc[s * H + h] + ad);
            const float w = __expf(l);
            den += w;
            const float4* xr = (const float4*)&g_xh[s * HCP + h * CP];
            const float4 v0 = xr[0];
            const float4 v1 = xr[1];
            agg0.x = fmaxf(agg0.x, w * v0.x);
            agg0.y = fmaxf(agg0.y, w * v0.y);
            agg0.z = fmaxf(agg0.z, w * v0.z);
            agg0.w = fmaxf(agg0.w, w * v0.w);
            agg1.x = fmaxf(agg1.x, w * v1.x);
            agg1.y = fmaxf(agg1.y, w * v1.y);
            agg1.z = fmaxf(agg1.z, w * v1.z);
        }
        const float inv = 1.0f / den;        // den > 0 (self loop guarantees deg>=1)
        sm[ln][h][0] = agg0.x * inv;
        sm[ln][h][1] = agg0.y * inv;
        sm[ln][h][2] = agg0.z * inv;
        sm[ln][h][3] = agg0.w * inv;
        sm[ln][h][4] = agg1.x * inv;
        sm[ln][h][5] = agg1.y * inv;
        sm[ln][h][6] = agg1.z * inv;
    }
    __syncthreads();

    if (MODE == 0) {
        // one thread per (node, channel)
        if (tid < 32 * C) {
            const int l2 = tid / C, c = tid % C;
            const int nn = blockIdx.x * 32 + l2;
            if (nn < NN) {
                float s = 0.0f;
#pragma unroll
                for (int hh = 0; hh < H; hh++) s += sm[l2][hh][c];
                out[nn * C + c] = fmaxf(s * (1.0f / H) + b[c], 0.0f);
            }
        }
    } else {
        // one thread per node: log_softmax over 7 classes
        if (tid < 32) {
            const int nn = blockIdx.x * 32 + tid;
            if (nn < NN) {
                float v[C];
#pragma unroll
                for (int c = 0; c < C; c++) {
                    float s = 0.0f;
#pragma unroll
                    for (int hh = 0; hh < H; hh++) s += sm[tid][hh][c];
                    v[c] = s * (1.0f / H) + b[c];
                }
                float mx = v[0];
#pragma unroll
                for (int c = 1; c < C; c++) mx = fmaxf(mx, v[c]);
                float se = 0.0f;
#pragma unroll
                for (int c = 0; c < C; c++) se += __expf(v[c] - mx);
                const float lse = mx + logf(se);
#pragma unroll
                for (int c = 0; c < C; c++) out[nn * C + c] = v[c] - lse;
            }
        }
    }
}

// ---------------- GEMM2: g_h[N,7] @ W2[7,98] -> g_xh (padded) ------------------
__global__ void k_gemm2(const float* __restrict__ W2) {
    const int i = blockIdx.x * blockDim.x + threadIdx.x;
    if (i >= NN * HC) return;
    const int n = i / HC, col = i % HC;
    float s = 0.0f;
#pragma unroll
    for (int k = 0; k < C; k++) s = fmaf(g_h[n * C + k], W2[k * HC + col], s);
    g_xh[n * HCP + (col / C) * CP + (col % C)] = s;
}

extern "C" void kernel_launch(void* const* d_in, const int* in_sizes, int n_in,
                              void* d_out, int out_size) {
    const float* x      = (const float*)d_in[0];
    const int*   ei     = (const int*)  d_in[1];
    const float* W1     = (const float*)d_in[2];
    const float* a_src1 = (const float*)d_in[3];
    const float* a_dst1 = (const float*)d_in[4];
    const float* b1     = (const float*)d_in[5];
    const float* W2     = (const float*)d_in[6];
    const float* a_src2 = (const float*)d_in[7];
    const float* a_dst2 = (const float*)d_in[8];
    const float* b2     = (const float*)d_in[9];
    float* out = (float*)d_out;

    const int EB = (ET + 255) / 256;
    const int SCAN_BLOCKS = (NN + 1023) / 1024;
    const int NB = (NN + 31) / 32;

    float* g_h_ptr;
    cudaGetSymbolAddress((void**)&g_h_ptr, g_h);

    // ----- CSR by destination (shared by both layers) -----
    k_zero   <<<(NN + 255) / 256, 256>>>();
    k_hist   <<<EB, 256>>>(ei);
    k_scan1  <<<SCAN_BLOCKS, 1024>>>();
    k_scan2  <<<1, 32>>>(SCAN_BLOCKS);
    k_scan3  <<<(NN + 255) / 256, 256>>>();
    k_scatter<<<EB, 256>>>(ei);

    // ----- layer 1 -----
    k_gemm1  <<<(NN + 63) / 64, 256>>>(x, W1);
    k_al     <<<(NN * H + 255) / 256, 256>>>(a_src1, a_dst1);
    k_node<0><<<NB, 448>>>(b1, g_h_ptr);

    // ----- layer 2 -----
    k_gemm2  <<<(NN * HC + 255) / 256, 256>>>(W2);
    k_al     <<<(NN * H + 255) / 256, 256>>>(a_src2, a_dst2);
    k_node<1><<<NB, 448>>>(b2, out);
}

// round 5
// speedup vs baseline: 12.6393x; 1.5074x over previous
#include <cuda_runtime.h>
#include <cuda_fp16.h>
#include <cstdint>
#include <math.h>

#define NN 100000
#define EE 1600000
#define ET 1700000      // edges + self loops
#define H 14
#define C 7
#define HC 98
#define CP 8            // padded channels
#define HCP 112         // H * CP
#define FIN 256

// ---------------- scratch (device globals; reused across both layers) ----------
__device__ __align__(16) __half g_xh[NN * HCP]; // projected features [N,H,8] fp16
__device__ float g_alsrc[NN * H];    // per-node src logits
__device__ float g_aldst[NN * H];    // per-node dst logits
__device__ float g_h[NN * C];        // layer-1 output features

// CSR-by-destination scratch
__device__ int g_cnt[NN];
__device__ int g_woff[NN];           // exclusive offsets (consumed by scatter)
__device__ int g_rp[NN + 1];
__device__ int g_bsum[128];
__device__ int g_csrc[ET];

__device__ __forceinline__ float lrelu(float v) {
    return v > 0.0f ? v : 0.2f * v;
}

__device__ __forceinline__ unsigned int f2tf(float f) {
    unsigned int r;
    asm("cvt.rna.tf32.f32 %0, %1;" : "=r"(r) : "f"(f));
    return r;
}

__device__ __forceinline__ void mma_tf32(float* c, const unsigned int* a,
                                         unsigned int b0, unsigned int b1) {
    asm volatile(
        "mma.sync.aligned.m16n8k8.row.col.f32.tf32.tf32.f32 "
        "{%0,%1,%2,%3},{%4,%5,%6,%7},{%8,%9},{%0,%1,%2,%3};"
        : "+f"(c[0]), "+f"(c[1]), "+f"(c[2]), "+f"(c[3])
        : "r"(a[0]), "r"(a[1]), "r"(a[2]), "r"(a[3]), "r"(b0), "r"(b1));
}

// ---------------- GEMM1 (TF32 MMA): x[N,256] @ W1[256,98] -> g_xh fp16 ---------
// BM=128, BN=112 (padded), 8 warps: 4(m)x2(n), warp tile 32x56
__global__ __launch_bounds__(256) void k_gemm1(const float* __restrict__ x,
                                               const float* __restrict__ W) {
    __shared__ float As[128][20];   // stride 20 -> conflict-free frag reads
    __shared__ float Bs[16][120];   // stride 120 -> conflict-free frag reads
    const int tid = threadIdx.x;
    const int warp = tid >> 5, lane = tid & 31;
    const int gid = lane >> 2, t4 = lane & 3;
    const int wm = warp >> 1, wn = warp & 1;
    const int bm = blockIdx.x * 128;
    const int rb0 = wm * 32;
    const int cb  = wn * 56;

    float acc[2][7][4];
#pragma unroll
    for (int mt = 0; mt < 2; mt++)
#pragma unroll
        for (int nt = 0; nt < 7; nt++)
#pragma unroll
            for (int q = 0; q < 4; q++) acc[mt][nt][q] = 0.0f;

    for (int k0 = 0; k0 < FIN; k0 += 16) {
        // load A tile 128x16 (float4 per thread x2)
#pragma unroll
        for (int i = 0; i < 2; i++) {
            const int idx = tid * 2 + i;        // 0..511
            const int row = idx >> 2, kq = idx & 3;
            float4 v = make_float4(0.f, 0.f, 0.f, 0.f);
            if (bm + row < NN) v = *(const float4*)&x[(size_t)(bm + row) * FIN + k0 + kq * 4];
            As[row][kq * 4 + 0] = v.x;
            As[row][kq * 4 + 1] = v.y;
            As[row][kq * 4 + 2] = v.z;
            As[row][kq * 4 + 3] = v.w;
        }
        // load B tile 16x112 padded (zero pad channel)
#pragma unroll
        for (int i = tid; i < 16 * HCP; i += 256) {
            const int k = i / HCP, cp = i % HCP;
            const int h = cp >> 3, c = cp & 7;
            Bs[k][cp] = (c < C) ? W[(size_t)(k0 + k) * HC + h * C + c] : 0.0f;
        }
        __syncthreads();
#pragma unroll
        for (int kk = 0; kk < 16; kk += 8) {
            unsigned int a[2][4];
#pragma unroll
            for (int mt = 0; mt < 2; mt++) {
                const int r = rb0 + mt * 16 + gid;
                a[mt][0] = f2tf(As[r][kk + t4]);
                a[mt][1] = f2tf(As[r + 8][kk + t4]);
                a[mt][2] = f2tf(As[r][kk + t4 + 4]);
                a[mt][3] = f2tf(As[r + 8][kk + t4 + 4]);
            }
#pragma unroll
            for (int nt = 0; nt < 7; nt++) {
                const unsigned int b0 = f2tf(Bs[kk + t4][cb + nt * 8 + gid]);
                const unsigned int b1 = f2tf(Bs[kk + t4 + 4][cb + nt * 8 + gid]);
#pragma unroll
                for (int mt = 0; mt < 2; mt++) mma_tf32(acc[mt][nt], a[mt], b0, b1);
            }
        }
        __syncthreads();
    }
    // store fp16
#pragma unroll
    for (int mt = 0; mt < 2; mt++) {
        const int r0 = bm + rb0 + mt * 16 + gid;
#pragma unroll
        for (int nt = 0; nt < 7; nt++) {
            const int col = cb + nt * 8 + t4 * 2;
            if (r0 < NN)
                *(__half2*)&g_xh[(size_t)r0 * HCP + col] =
                    __floats2half2_rn(acc[mt][nt][0], acc[mt][nt][1]);
            if (r0 + 8 < NN)
                *(__half2*)&g_xh[(size_t)(r0 + 8) * HCP + col] =
                    __floats2half2_rn(acc[mt][nt][2], acc[mt][nt][3]);
        }
    }
}

// ---------------- per-node attention logits (fp16 xh) --------------------------
__global__ void k_al(const float* __restrict__ a_src, const float* __restrict__ a_dst) {
    const int i = blockIdx.x * blockDim.x + threadIdx.x;
    if (i >= NN * H) return;
    const int n = i / H, h = i % H;
    const uint4 u = *(const uint4*)&g_xh[(size_t)n * HCP + h * CP];
    const __half2* hp = (const __half2*)&u;
    float xv[8];
    float2 f;
    f = __half22float2(hp[0]); xv[0] = f.x; xv[1] = f.y;
    f = __half22float2(hp[1]); xv[2] = f.x; xv[3] = f.y;
    f = __half22float2(hp[2]); xv[4] = f.x; xv[5] = f.y;
    f = __half22float2(hp[3]); xv[6] = f.x;
    float s1 = 0.0f, s2 = 0.0f;
#pragma unroll
    for (int c = 0; c < C; c++) {
        s1 = fmaf(xv[c], a_src[h * C + c], s1);
        s2 = fmaf(xv[c], a_dst[h * C + c], s2);
    }
    g_alsrc[i] = s1;
    g_aldst[i] = s2;
}

// ---------------- CSR build ----------------------------------------------------
__global__ void k_zero() {
    const int i = blockIdx.x * blockDim.x + threadIdx.x;
    if (i < NN) g_cnt[i] = 0;
}

__global__ void k_hist(const int* __restrict__ ei) {
    const int e = blockIdx.x * blockDim.x + threadIdx.x;
    if (e >= ET) return;
    const int d = (e < EE) ? ei[EE + e] : (e - EE);
    atomicAdd(&g_cnt[d], 1);
}

__global__ void k_scan1() {
    __shared__ int sm[1024];
    const int t = threadIdx.x;
    const int i = blockIdx.x * 1024 + t;
    int v = (i < NN) ? g_cnt[i] : 0;
    sm[t] = v;
#pragma unroll
    for (int off = 1; off < 1024; off <<= 1) {
        __syncthreads();
        int add = (t >= off) ? sm[t - off] : 0;
        __syncthreads();
        sm[t] += add;
    }
    __syncthreads();
    if (i < NN) g_rp[i + 1] = sm[t];
    if (t == 1023) g_bsum[blockIdx.x] = sm[1023];
}

__global__ void k_scan2(int nblocks) {
    const int lane = threadIdx.x;
    int run = 0;
    for (int base = 0; base < nblocks; base += 32) {
        const int idx = base + lane;
        const int orig = (idx < nblocks) ? g_bsum[idx] : 0;
        int v = orig;
#pragma unroll
        for (int off = 1; off < 32; off <<= 1) {
            const int t = __shfl_up_sync(0xffffffffu, v, off);
            if (lane >= off) v += t;
        }
        if (idx < nblocks) g_bsum[idx] = run + v - orig;  // exclusive
        run += __shfl_sync(0xffffffffu, v, 31);
    }
}

__global__ void k_scan3() {
    const int i = blockIdx.x * blockDim.x + threadIdx.x;
    if (i == 0) g_rp[0] = 0;
    if (i < NN) {
        const int inc = g_rp[i + 1] + g_bsum[i >> 10];
        g_rp[i + 1] = inc;
        g_woff[i] = inc - g_cnt[i];
    }
}

__global__ void k_scatter(const int* __restrict__ ei) {
    const int e = blockIdx.x * blockDim.x + threadIdx.x;
    if (e >= ET) return;
    int s, d;
    if (e < EE) { s = ei[e]; d = ei[EE + e]; } else { s = d = e - EE; }
    const int pos = atomicAdd(&g_woff[d], 1);
    g_csrc[pos] = s;
}

// ---------------- fused node pass: softmax + max agg + head reduce -------------
// MODE 0: g_h = relu(mean_head + bias); MODE 1: out = log_softmax(mean_head + bias)
template<int MODE>
__global__ void k_node(const float* __restrict__ b, float* __restrict__ out) {
    __shared__ float sm[32][H][CP];          // 14 KB
    const int tid = threadIdx.x;             // 448 = 32 nodes * 14 heads
    const int ln = tid / H;
    const int h  = tid % H;
    const int n  = blockIdx.x * 32 + ln;

    if (n < NN) {
        const int beg = g_rp[n], end = g_rp[n + 1];
        const float ad = g_aldst[n * H + h];
        float den = 0.0f;
        float a0 = -INFINITY, a1 = -INFINITY, a2 = -INFINITY, a3 = -INFINITY;
        float a4 = -INFINITY, a5 = -INFINITY, a6 = -INFINITY;
        for (int j = beg; j < end; j++) {
            const int s = g_csrc[j];
            const float l = lrelu(g_alsrc[s * H + h] + ad);
            const float w = __expf(l);
            den += w;
            const uint4 u = *(const uint4*)&g_xh[(size_t)s * HCP + h * CP];
            const __half2* hp = (const __half2*)&u;
            const float2 f0 = __half22float2(hp[0]);
            const float2 f1 = __half22float2(hp[1]);
            const float2 f2 = __half22float2(hp[2]);
            const float2 f3 = __half22float2(hp[3]);
            a0 = fmaxf(a0, w * f0.x);
            a1 = fmaxf(a1, w * f0.y);
            a2 = fmaxf(a2, w * f1.x);
            a3 = fmaxf(a3, w * f1.y);
            a4 = fmaxf(a4, w * f2.x);
            a5 = fmaxf(a5, w * f2.y);
            a6 = fmaxf(a6, w * f3.x);
        }
        const float inv = 1.0f / den;        // den > 0 (self loop => deg >= 1)
        sm[ln][h][0] = a0 * inv;
        sm[ln][h][1] = a1 * inv;
        sm[ln][h][2] = a2 * inv;
        sm[ln][h][3] = a3 * inv;
        sm[ln][h][4] = a4 * inv;
        sm[ln][h][5] = a5 * inv;
        sm[ln][h][6] = a6 * inv;
    }
    __syncthreads();

    if (MODE == 0) {
        if (tid < 32 * C) {
            const int l2 = tid / C, c = tid % C;
            const int nn = blockIdx.x * 32 + l2;
            if (nn < NN) {
                float s = 0.0f;
#pragma unroll
                for (int hh = 0; hh < H; hh++) s += sm[l2][hh][c];
                out[nn * C + c] = fmaxf(s * (1.0f / H) + b[c], 0.0f);
            }
        }
    } else {
        if (tid < 32) {
            const int nn = blockIdx.x * 32 + tid;
            if (nn < NN) {
                float v[C];
#pragma unroll
                for (int c = 0; c < C; c++) {
                    float s = 0.0f;
#pragma unroll
                    for (int hh = 0; hh < H; hh++) s += sm[tid][hh][c];
                    v[c] = s * (1.0f / H) + b[c];
                }
                float mx = v[0];
#pragma unroll
                for (int c = 1; c < C; c++) mx = fmaxf(mx, v[c]);
                float se = 0.0f;
#pragma unroll
                for (int c = 0; c < C; c++) se += __expf(v[c] - mx);
                const float lse = mx + logf(se);
#pragma unroll
                for (int c = 0; c < C; c++) out[nn * C + c] = v[c] - lse;
            }
        }
    }
}

// ---------------- GEMM2: g_h[N,7] @ W2[7,98] -> g_xh fp16 (padded) -------------
__global__ void k_gemm2(const float* __restrict__ W2) {
    const int i = blockIdx.x * blockDim.x + threadIdx.x;
    if (i >= NN * HC) return;
    const int n = i / HC, col = i % HC;
    float s = 0.0f;
#pragma unroll
    for (int k = 0; k < C; k++) s = fmaf(g_h[n * C + k], W2[k * HC + col], s);
    g_xh[(size_t)n * HCP + (col / C) * CP + (col % C)] = __float2half_rn(s);
}

extern "C" void kernel_launch(void* const* d_in, const int* in_sizes, int n_in,
                              void* d_out, int out_size) {
    const float* x      = (const float*)d_in[0];
    const int*   ei     = (const int*)  d_in[1];
    const float* W1     = (const float*)d_in[2];
    const float* a_src1 = (const float*)d_in[3];
    const float* a_dst1 = (const float*)d_in[4];
    const float* b1     = (const float*)d_in[5];
    const float* W2     = (const float*)d_in[6];
    const float* a_src2 = (const float*)d_in[7];
    const float* a_dst2 = (const float*)d_in[8];
    const float* b2     = (const float*)d_in[9];
    float* out = (float*)d_out;

    const int EB = (ET + 255) / 256;
    const int SCAN_BLOCKS = (NN + 1023) / 1024;
    const int NB = (NN + 31) / 32;

    float* g_h_ptr;
    cudaGetSymbolAddress((void**)&g_h_ptr, g_h);

    // ----- CSR by destination (shared by both layers) -----
    k_zero   <<<(NN + 255) / 256, 256>>>();
    k_hist   <<<EB, 256>>>(ei);
    k_scan1  <<<SCAN_BLOCKS, 1024>>>();
    k_scan2  <<<1, 32>>>(SCAN_BLOCKS);
    k_scan3  <<<(NN + 255) / 256, 256>>>();
    k_scatter<<<EB, 256>>>(ei);

    // ----- layer 1 -----
    k_gemm1  <<<(NN + 127) / 128, 256>>>(x, W1);
    k_al     <<<(NN * H + 255) / 256, 256>>>(a_src1, a_dst1);
    k_node<0><<<NB, 448>>>(b1, g_h_ptr);

    // ----- layer 2 -----
    k_gemm2  <<<(NN * HC + 255) / 256, 256>>>(W2);
    k_al     <<<(NN * H + 255) / 256, 256>>>(a_src2, a_dst2);
    k_node<1><<<NB, 448>>>(b2, out);
}